// round 3
// baseline (speedup 1.0000x reference)
#include <cuda_runtime.h>
#include <cstdint>

#define ROW_L 2048
#define S_OUT 65
#define OUT_PER_ROW (S_OUT * S_OUT)   // 4225
#define NTHREADS 256

__global__ __launch_bounds__(NTHREADS)
void rp_kernel(const float* __restrict__ x, float* __restrict__ out)
{
    const int row = blockIdx.x;
    const float* __restrict__ xr = x + (size_t)row * ROW_L;

    __shared__ double s_red_d[8];
    __shared__ int    s_red_mn[8];
    __shared__ int    s_red_mx[8];
    __shared__ float  s_mean, s_std;
    __shared__ int    s_first, s_last;
    __shared__ float  s_head[68];   // first 65 (padded to 68) raw values
    __shared__ float  s_xs[S_OUT];  // normalized first-65 (NaN where invalid)

    const int tid  = threadIdx.x;
    const int lane = tid & 31;
    const int warp = tid >> 5;

    // ---- load: each thread grabs 8 floats via 2x float4 (front-batched MLP) ----
    float4 a = ((const float4*)xr)[tid];          // elements 4*tid .. 4*tid+3
    float4 b = ((const float4*)xr)[tid + 256];    // elements 1024+4*tid ..

    if (tid < 17) ((float4*)s_head)[tid] = a;     // covers indices 0..67

    const int ia0 = tid * 4;
    const int ib0 = 1024 + tid * 4;

    float va[8] = {a.x, a.y, a.z, a.w, b.x, b.y, b.z, b.w};

    // ---- pass 1: total sum (== masked sum, zeros outside window) + nz extent ----
    int mn = ROW_L, mx = -1;
    double s = 0.0;
#pragma unroll
    for (int k = 0; k < 8; k++) {
        float v = va[k];
        int idx = (k < 4) ? (ia0 + k) : (ib0 + (k - 4));
        s += (double)v;
        if (v != 0.0f) {
            mn = min(mn, idx);
            mx = max(mx, idx);
        }
    }
#pragma unroll
    for (int off = 16; off; off >>= 1) {
        s  += __shfl_down_sync(0xffffffffu, s, off);
        mn  = min(mn, __shfl_down_sync(0xffffffffu, mn, off));
        mx  = max(mx, __shfl_down_sync(0xffffffffu, mx, off));
    }
    if (lane == 0) { s_red_d[warp] = s; s_red_mn[warp] = mn; s_red_mx[warp] = mx; }
    __syncthreads();

    if (tid == 0) {
        double st = 0.0; int m1 = ROW_L, m2 = -1;
#pragma unroll
        for (int w = 0; w < 8; w++) {
            st += s_red_d[w];
            m1 = min(m1, s_red_mn[w]);
            m2 = max(m2, s_red_mx[w]);
        }
        s_first = m1; s_last = m2;
        float cnt = (m2 >= m1) ? (float)(m2 - m1 + 1) : 1.0f;
        s_mean = (float)(st / (double)cnt);
    }
    __syncthreads();

    const int   first = s_first;
    const int   last  = s_last;
    const float mean  = s_mean;

    // ---- pass 2: sum of (x-mean)^2 over valid window only ----
    double vs = 0.0;
#pragma unroll
    for (int k = 0; k < 8; k++) {
        int idx = (k < 4) ? (ia0 + k) : (ib0 + (k - 4));
        if (idx >= first && idx <= last) {
            float d = va[k] - mean;
            vs += (double)d * (double)d;
        }
    }
#pragma unroll
    for (int off = 16; off; off >>= 1)
        vs += __shfl_down_sync(0xffffffffu, vs, off);
    if (lane == 0) s_red_d[warp] = vs;
    __syncthreads();

    if (tid == 0) {
        double vt = 0.0;
#pragma unroll
        for (int w = 0; w < 8; w++) vt += s_red_d[w];
        float cnt = (last >= first) ? (float)(last - first + 1) : 1.0f;
        float var = (float)(vt / (double)cnt);
        s_std = fmaxf(sqrtf(var), 1e-6f);
    }
    __syncthreads();

    const float stdv = s_std;

    // ---- normalize first 65; NaN sentinel outside mask so pair test auto-fails ----
    if (tid < S_OUT) {
        bool valid = (last >= first) && (tid >= first) && (tid <= last);
        s_xs[tid] = valid ? (s_head[tid] - mean) / stdv
                          : __int_as_float(0x7fffffff); // NaN
    }
    __syncthreads();

    // ---- output: 65x65 pairwise threshold, coalesced streaming stores ----
    float* __restrict__ ob = out + (size_t)row * OUT_PER_ROW;
    for (int e = tid; e < OUT_PER_ROW; e += NTHREADS) {
        int i = e / S_OUT;
        int j = e - i * S_OUT;
        float d = fabsf(s_xs[i] - s_xs[j]);
        ob[e] = (d < 0.2f) ? 1.0f : 0.0f;   // NaN compares false -> 0
    }
}

extern "C" void kernel_launch(void* const* d_in, const int* in_sizes, int n_in,
                              void* d_out, int out_size)
{
    const float* x = (const float*)d_in[0];
    float* out = (float*)d_out;
    int rows = in_sizes[0] / ROW_L;   // N*C = 16384
    rp_kernel<<<rows, NTHREADS>>>(x, out);
}

// round 4
// speedup vs baseline: 1.1839x; 1.1839x over previous
#include <cuda_runtime.h>
#include <cstdint>

#define ROW_L 2048
#define S_OUT 65
#define OUT_PER_ROW (S_OUT * S_OUT)   // 4225
#define NTHREADS 256

__device__ __forceinline__ float pair_val(const float* xs, int e)
{
    int i = e / S_OUT;
    int j = e - i * S_OUT;
    float d = fabsf(xs[i] - xs[j]);
    return (d < 0.2f) ? 1.0f : 0.0f;   // NaN sentinel compares false -> 0
}

__global__ __launch_bounds__(NTHREADS)
void rp_kernel(const float* __restrict__ x, float* __restrict__ out)
{
    const int row = blockIdx.x;
    const float* __restrict__ xr = x + (size_t)row * ROW_L;

    __shared__ double s_red_s[8];
    __shared__ double s_red_q[8];
    __shared__ int    s_red_mn[8];
    __shared__ int    s_red_mx[8];
    __shared__ float  s_mean, s_std;
    __shared__ int    s_first, s_last;
    __shared__ float  s_head[68];   // first 65 (padded to 68) raw values
    __shared__ float  s_xs[S_OUT];  // normalized first-65 (NaN where invalid)

    const int tid  = threadIdx.x;
    const int lane = tid & 31;
    const int warp = tid >> 5;

    // ---- load: each thread grabs 8 floats via 2x float4 (streaming) ----
    float4 a = __ldcs(((const float4*)xr) + tid);          // elems 4*tid..+3
    float4 b = __ldcs(((const float4*)xr) + tid + 256);    // elems 1024+4*tid..

    if (tid < 17) ((float4*)s_head)[tid] = a;              // covers idx 0..67

    const int ia0 = tid * 4;
    const int ib0 = 1024 + tid * 4;

    float va[8] = {a.x, a.y, a.z, a.w, b.x, b.y, b.z, b.w};

    // ---- single pass: sum, sum-of-squares (masked == full-row, zeros outside
    //      window contribute nothing), and nonzero extent ----
    int mn = ROW_L, mx = -1;
    double s = 0.0, q = 0.0;
#pragma unroll
    for (int k = 0; k < 8; k++) {
        float v = va[k];
        int idx = (k < 4) ? (ia0 + k) : (ib0 + (k - 4));
        double dv = (double)v;
        s += dv;
        q += dv * dv;
        if (v != 0.0f) {
            mn = min(mn, idx);
            mx = max(mx, idx);
        }
    }
#pragma unroll
    for (int off = 16; off; off >>= 1) {
        s  += __shfl_down_sync(0xffffffffu, s, off);
        q  += __shfl_down_sync(0xffffffffu, q, off);
        mn  = min(mn, __shfl_down_sync(0xffffffffu, mn, off));
        mx  = max(mx, __shfl_down_sync(0xffffffffu, mx, off));
    }
    if (lane == 0) {
        s_red_s[warp] = s; s_red_q[warp] = q;
        s_red_mn[warp] = mn; s_red_mx[warp] = mx;
    }
    __syncthreads();

    if (tid == 0) {
        double st = 0.0, qt = 0.0; int m1 = ROW_L, m2 = -1;
#pragma unroll
        for (int w = 0; w < 8; w++) {
            st += s_red_s[w];
            qt += s_red_q[w];
            m1 = min(m1, s_red_mn[w]);
            m2 = max(m2, s_red_mx[w]);
        }
        s_first = m1; s_last = m2;
        double cnt = (m2 >= m1) ? (double)(m2 - m1 + 1) : 1.0;
        double meand = st / cnt;
        double vard  = qt / cnt - meand * meand;
        if (vard < 0.0) vard = 0.0;
        s_mean = (float)meand;
        s_std  = fmaxf(sqrtf((float)vard), 1e-6f);
    }
    __syncthreads();

    const int   first = s_first;
    const int   last  = s_last;
    const float mean  = s_mean;
    const float stdv  = s_std;

    // ---- normalize first 65; NaN sentinel outside mask ----
    if (tid < S_OUT) {
        bool valid = (last >= first) && (tid >= first) && (tid <= last);
        s_xs[tid] = valid ? (s_head[tid] - mean) / stdv
                          : __int_as_float(0x7fffffff); // NaN
    }
    __syncthreads();

    // ---- output: 65x65 pairwise threshold, STG.128 with alignment peel ----
    float* __restrict__ ob = out + (size_t)row * OUT_PER_ROW;
    const int mis  = (int)(((uintptr_t)ob >> 2) & 3);   // float misalignment
    const int head = (4 - mis) & 3;

    if (tid < head)
        ob[tid] = pair_val(s_xs, tid);

    const int nrem = OUT_PER_ROW - head;
    const int nvec = nrem >> 2;          // float4 count
    const int tail = nrem & 3;
    float4* __restrict__ vb = (float4*)(ob + head);

    for (int v = tid; v < nvec; v += NTHREADS) {
        int e = head + 4 * v;
        float4 r;
        r.x = pair_val(s_xs, e);
        r.y = pair_val(s_xs, e + 1);
        r.z = pair_val(s_xs, e + 2);
        r.w = pair_val(s_xs, e + 3);
        __stcs(vb + v, r);
    }

    if (tid < tail) {
        int e = head + 4 * nvec + tid;
        ob[e] = pair_val(s_xs, e);
    }
}

extern "C" void kernel_launch(void* const* d_in, const int* in_sizes, int n_in,
                              void* d_out, int out_size)
{
    const float* x = (const float*)d_in[0];
    float* out = (float*)d_out;
    int rows = in_sizes[0] / ROW_L;   // N*C = 16384
    rp_kernel<<<rows, NTHREADS>>>(x, out);
}

// round 7
// speedup vs baseline: 4.1031x; 3.4657x over previous
#include <cuda_runtime.h>
#include <cstdint>

#define ROW_L 2048
#define S_OUT 65
#define OUT_PER_ROW 4225
#define ROWS_PER_CTA 4
#define NT 256

#define SM_OUT_BYTES (OUT_PER_ROW * ROWS_PER_CTA * 4)   // 67600
#define OFF_HEAD  67600                                  // 4 x 68 floats
#define OFF_XS    (OFF_HEAD + 1088)                      // 4 x 68 floats (16B aligned rows)
#define OFF_RED   (OFF_XS + 1088)                        // 4 x 2 x 2 doubles
#define OFF_REDI  (OFF_RED + 128)                        // 4 x 2 x 2 ints
#define OFF_STAT  (OFF_REDI + 64)                        // 4 x 2 floats
#define SMEM_TOTAL (OFF_STAT + 32)                       // 70000 B

__device__ __forceinline__ uint32_t s2u(const void* p) {
    return (uint32_t)__cvta_generic_to_shared(p);
}

__device__ __forceinline__ float thresh_val(float xi, float xj) {
    // 1.0f iff |xi-xj| < 0.2f, else 0.0f; NaN -> 0.0f.
    // 0.2f * 2^100 is exact; (0.2f - |d|) is Sterbenz-exact near the threshold,
    // so sign of the fma result matches (|d| < 0.2f) bit-exactly.
    const float BIG  = 0x1p100f;
    const float CBIG = 0.2f * 0x1p100f;
    return __saturatef(fmaf(fabsf(xi - xj), -BIG, CBIG));
}

__global__ __launch_bounds__(NT)
void rp_kernel(const float* __restrict__ x, float* __restrict__ out)
{
    extern __shared__ __align__(16) char smem[];
    float*   s_out  = (float*)smem;
    float  (*s_head)[68]   = (float(*)[68])(smem + OFF_HEAD);
    float  (*s_xs)[68]     = (float(*)[68])(smem + OFF_XS);
    double (*s_red)[2][2]  = (double(*)[2][2])(smem + OFF_RED);
    int    (*s_redi)[2][2] = (int(*)[2][2])(smem + OFF_REDI);
    float  (*s_stat)[2]    = (float(*)[2])(smem + OFF_STAT);

    const int tid  = threadIdx.x;
    const int g    = tid >> 6;          // row-in-CTA (0..3)
    const int t    = tid & 63;          // thread-in-row-group
    const int half = (tid >> 5) & 1;    // which warp of the 2-warp row group

    const float* __restrict__ xr =
        x + ((size_t)blockIdx.x * ROWS_PER_CTA + g) * ROW_L;

    // ---- load: 8 x LDG.128 per thread, front-batched ----
    float4 v[8];
#pragma unroll
    for (int k = 0; k < 8; k++)
        v[k] = __ldcs((const float4*)xr + k * 64 + t);

    if (t < 17) ((float4*)s_head[g])[t] = v[0];   // first 68 floats of row

    // ---- per-thread fp32 pairwise sums + nonzero extent ----
    float s4[8], q4[8];
    int mn = ROW_L, mx = -1;
#pragma unroll
    for (int k = 0; k < 8; k++) {
        float4 a = v[k];
        s4[k] = (a.x + a.y) + (a.z + a.w);
        q4[k] = fmaf(a.x, a.x, fmaf(a.y, a.y, fmaf(a.z, a.z, a.w * a.w)));
        int base = (k * 64 + t) * 4;
        if (a.x != 0.f) { mn = min(mn, base    ); mx = max(mx, base    ); }
        if (a.y != 0.f) { mn = min(mn, base + 1); mx = max(mx, base + 1); }
        if (a.z != 0.f) { mn = min(mn, base + 2); mx = max(mx, base + 2); }
        if (a.w != 0.f) { mn = min(mn, base + 3); mx = max(mx, base + 3); }
    }
    float s8 = ((s4[0]+s4[1]) + (s4[2]+s4[3])) + ((s4[4]+s4[5]) + (s4[6]+s4[7]));
    float q8 = ((q4[0]+q4[1]) + (q4[2]+q4[3])) + ((q4[4]+q4[5]) + (q4[6]+q4[7]));

    // ---- fp64 shuffle tree (accuracy-preserving, cheap: 10 DADD/thread) ----
    double sd = (double)s8, qd = (double)q8;
#pragma unroll
    for (int off = 16; off; off >>= 1) {
        sd += __shfl_down_sync(0xffffffffu, sd, off);
        qd += __shfl_down_sync(0xffffffffu, qd, off);
        mn  = min(mn, __shfl_down_sync(0xffffffffu, mn, off));
        mx  = max(mx, __shfl_down_sync(0xffffffffu, mx, off));
    }
    if ((tid & 31) == 0) {
        s_red[g][half][0]  = sd;  s_red[g][half][1]  = qd;
        s_redi[g][half][0] = mn;  s_redi[g][half][1] = mx;
    }
    __syncthreads();

    // ---- per-row stats (4 threads) ----
    if (tid < ROWS_PER_CTA) {
        int r = tid;
        double S = s_red[r][0][0] + s_red[r][1][0];
        double Q = s_red[r][0][1] + s_red[r][1][1];
        int m1 = min(s_redi[r][0][0], s_redi[r][1][0]);
        int m2 = max(s_redi[r][0][1], s_redi[r][1][1]);
        double cnt  = (m2 >= m1) ? (double)(m2 - m1 + 1) : 1.0;
        double mean = S / cnt;
        double var  = Q / cnt - mean * mean;
        if (var < 0.0) var = 0.0;
        s_stat[r][0] = (float)mean;
        s_stat[r][1] = fmaxf(sqrtf((float)var), 1e-6f);
        s_redi[r][0][0] = m1;      // combined extent for normalize step
        s_redi[r][0][1] = m2;
    }
    __syncthreads();

    // ---- normalize first 65 per row; NaN sentinel outside valid window ----
    for (int e = tid; e < ROWS_PER_CTA * S_OUT; e += NT) {
        int r = e / S_OUT;
        int i = e - r * S_OUT;
        int m1 = s_redi[r][0][0], m2 = s_redi[r][0][1];
        bool valid = (m2 >= m1) && (i >= m1) && (i <= m2);
        s_xs[r][i] = valid ? (s_head[r][i] - s_stat[r][0]) / s_stat[r][1]
                           : __int_as_float(0x7fffffff);   // NaN
    }
    __syncthreads();

    // ---- output compute into SMEM staging ----
    // thread (g, t): i-row t of CTA-row g. Lane stores stride 65 floats -> 65 mod 32
    // banks = conflict-free. xs[j] chunk is a warp-uniform LDS.128 broadcast.
    {
        float xi = s_xs[g][t];
        float* dst = s_out + g * OUT_PER_ROW + t * S_OUT;
        const float4* xs4 = (const float4*)s_xs[g];
#pragma unroll
        for (int jc = 0; jc < 16; jc++) {
            float4 b = xs4[jc];
            dst[jc * 4 + 0] = thresh_val(xi, b.x);
            dst[jc * 4 + 1] = thresh_val(xi, b.y);
            dst[jc * 4 + 2] = thresh_val(xi, b.z);
            dst[jc * 4 + 3] = thresh_val(xi, b.w);
        }
        dst[64] = thresh_val(xi, s_xs[g][64]);
    }
    if (tid < ROWS_PER_CTA) {     // the i = 64 rows
        int r = tid;
        float xi = s_xs[r][64];
        float* dst = s_out + r * OUT_PER_ROW + 64 * S_OUT;
        const float4* xs4 = (const float4*)s_xs[r];
#pragma unroll
        for (int jc = 0; jc < 16; jc++) {
            float4 b = xs4[jc];
            dst[jc * 4 + 0] = thresh_val(xi, b.x);
            dst[jc * 4 + 1] = thresh_val(xi, b.y);
            dst[jc * 4 + 2] = thresh_val(xi, b.z);
            dst[jc * 4 + 3] = thresh_val(xi, b.w);
        }
        dst[64] = thresh_val(xi, s_xs[r][64]);
    }
    __syncthreads();

    // ---- bulk TMA store: SMEM -> GMEM, zero per-element STG issue cost ----
    if (tid == 0) {
        asm volatile("fence.proxy.async.shared::cta;" ::: "memory");
        uint64_t gdst = (uint64_t)(out + (size_t)blockIdx.x * (OUT_PER_ROW * ROWS_PER_CTA));
        uint32_t ssrc = s2u(s_out);
        asm volatile("cp.async.bulk.global.shared::cta.bulk_group [%0], [%1], %2;"
                     :: "l"(gdst), "r"(ssrc), "n"(SM_OUT_BYTES) : "memory");
        asm volatile("cp.async.bulk.commit_group;" ::: "memory");
        asm volatile("cp.async.bulk.wait_group 0;" ::: "memory");
    }
}

extern "C" void kernel_launch(void* const* d_in, const int* in_sizes, int n_in,
                              void* d_out, int out_size)
{
    const float* x = (const float*)d_in[0];
    float* out = (float*)d_out;
    int rows = in_sizes[0] / ROW_L;            // 16384
    int blocks = rows / ROWS_PER_CTA;          // 4096
    cudaFuncSetAttribute(rp_kernel, cudaFuncAttributeMaxDynamicSharedMemorySize,
                         SMEM_TOTAL);
    rp_kernel<<<blocks, NT, SMEM_TOTAL>>>(x, out);
}